// round 12
// baseline (speedup 1.0000x reference)
#include <cuda_runtime.h>
#include <math.h>
#include <stdint.h>

#define NTHREADS 512
#define NGROUPS  4
#define TILE_E   16          // edges per group-tile

// fragment-ordered tf32 weights in device-global scratch (L1/L2-cached)
#define W1F_OFF   0
#define W2F_OFF   8192
#define WRRF_OFF  16384
#define WRCF_OFF  24576
__device__ uint32_t g_Wf[40960];

// ---------------- smem layout (bytes): activations only ----------------
// per group: A0 = 16 x 68 f = 4352 B, A1 = 16 x 132 f = 8448 B
#define OFF_A0    0                       // 4 x 4352  = 17408
#define OFF_A1    17408                   // 4 x 8448  = 33792
#define OFF_B1    51200                   // 128 f
#define OFF_B2    51712                   // 64 f
#define OFF_BRR   51968                   // 128 f
#define OFF_BRC   52480                   // 128 f
#define OFF_OBS   52992                   // 4 x 16 int
#define OFF_J     53248                   // 4 x 16 int
#define SMEM_BYTES 53504

#define STR0 68    // word stride, A0: rows 4 banks apart -> LDSM conflict-free
#define STR1 132   // word stride, A1

// Fast exact-GELU: erf via Abramowitz-Stegun 7.1.26 (|eps| <= 1.5e-7)
__device__ __forceinline__ float gelu_f(float x) {
    const float ax = fabsf(x);
    const float z  = ax * 0.70710678118654752f;
    const float den = fmaf(0.3275911f, z, 1.0f);
    float t;
    asm("rcp.approx.f32 %0, %1;" : "=f"(t) : "f"(den));
    float p = fmaf(t, 1.061405429f, -1.453152027f);
    p = fmaf(t, p, 1.421413741f);
    p = fmaf(t, p, -0.284496736f);
    p = fmaf(t, p, 0.254829592f);
    p = p * t;
    const float e = __expf(-z * z);
    const float erfz = fmaf(-e, p, 1.0f);
    return fmaf(0.5f * ax, erfz, 0.5f * x);
}

__device__ __forceinline__ uint32_t f2tf(float x) {
    uint32_t r;
    asm("cvt.rna.tf32.f32 %0, %1;" : "=r"(r) : "f"(x));
    return r;
}

__device__ __forceinline__ void mma8(float d[4], uint32_t a0, uint32_t a1,
                                     uint32_t a2, uint32_t a3,
                                     uint32_t b0, uint32_t b1) {
    asm volatile(
        "mma.sync.aligned.m16n8k8.row.col.f32.tf32.tf32.f32 "
        "{%0,%1,%2,%3}, {%4,%5,%6,%7}, {%8,%9}, {%0,%1,%2,%3};"
        : "+f"(d[0]), "+f"(d[1]), "+f"(d[2]), "+f"(d[3])
        : "r"(a0), "r"(a1), "r"(a2), "r"(a3), "r"(b0), "r"(b1));
}

__device__ __forceinline__ void ldsm4(uint32_t& a0, uint32_t& a1,
                                      uint32_t& a2, uint32_t& a3, uint32_t addr) {
    asm volatile("ldmatrix.sync.aligned.m8n8.x4.shared.b16 {%0,%1,%2,%3}, [%4];"
                 : "=r"(a0), "=r"(a1), "=r"(a2), "=r"(a3) : "r"(addr));
}

#define GBAR() asm volatile("bar.sync %0, 128;" :: "r"(grp + 1) : "memory")

// one element of W [K,N] row-major -> tf32 B-fragment order
__device__ __forceinline__ void pf1(const float* __restrict__ W, int K, int N,
                                    uint32_t* __restrict__ dst, int j) {
    const int K8 = K >> 3;
    const int reg  = j & 1;
    const int lane = (j >> 1) & 31;
    const int fk   = j >> 6;
    const int ks   = fk % K8;
    const int nt   = fk / K8;
    const int k = ks * 8 + (lane & 3) + reg * 4;
    const int n = nt * 8 + (lane >> 2);
    dst[j] = f2tf(W[k * N + n]);
}

__global__ void prep_weights(const float* __restrict__ W1, const float* __restrict__ W2,
                             const float* __restrict__ Wrr, const float* __restrict__ Wrc) {
    int i = blockIdx.x * blockDim.x + threadIdx.x;
    for (; i < 40960; i += gridDim.x * blockDim.x) {
        if (i < 8192)       pf1(W1,   64, 128, g_Wf + W1F_OFF,  i);
        else if (i < 16384) pf1(W2,  128,  64, g_Wf + W2F_OFF,  i - 8192);
        else if (i < 24576) pf1(Wrr,  64, 128, g_Wf + WRRF_OFF, i - 16384);
        else                pf1(Wrc, 128, 128, g_Wf + WRCF_OFF, i - 24576);
    }
}

__global__ void __launch_bounds__(NTHREADS, 1)
attr_rel_mma(const float* __restrict__ km,  const int* __restrict__ obsI,
             const int* __restrict__ omI,   const int* __restrict__ atI,
             const float* __restrict__ obsE, const float* __restrict__ fcorr,
             const float* __restrict__ b1,  const float* __restrict__ b2,
             const float* __restrict__ brr, const float* __restrict__ brc,
             float* __restrict__ out, int E)
{
    extern __shared__ char smem[];
    float* sb1  = (float*)(smem + OFF_B1);
    float* sb2  = (float*)(smem + OFF_B2);
    float* sbrr = (float*)(smem + OFF_BRR);
    float* sbrc = (float*)(smem + OFF_BRC);

    const int tid  = threadIdx.x;
    const int warp = tid >> 5;
    const int lane = tid & 31;
    const int grp  = warp >> 2;          // work-group 0..3
    const int wl   = warp & 3;           // N-group within work-group
    const int tg   = tid & 127;          // thread id within group
    const int r    = lane >> 2;
    const int q    = lane & 3;

    uint32_t* A0 = (uint32_t*)(smem + OFF_A0) + grp * (TILE_E * STR0);
    uint32_t* A1 = (uint32_t*)(smem + OFF_A1) + grp * (TILE_E * STR1);
    int* sObs = (int*)(smem + OFF_OBS) + grp * TILE_E;
    int* sJ   = (int*)(smem + OFF_J)   + grp * TILE_E;

    const uint32_t A0u = (uint32_t)__cvta_generic_to_shared(A0);
    const uint32_t A1u = (uint32_t)__cvta_generic_to_shared(A1);
    const int rowoff = (lane & 7) + ((lane >> 3) & 1) * 8;
    const int coloff = (lane >> 4) << 2;

    const uint32_t* W1f  = g_Wf + W1F_OFF;
    const uint32_t* W2f  = g_Wf + W2F_OFF;
    const uint32_t* Wrrf = g_Wf + WRRF_OFF;
    const uint32_t* Wrcf = g_Wf + WRCF_OFF;

    for (int i = tid; i < 128; i += NTHREADS) sb1[i]  = b1[i];
    for (int i = tid; i < 64;  i += NTHREADS) sb2[i]  = b2[i];
    for (int i = tid; i < 128; i += NTHREADS) sbrr[i] = brr[i];
    for (int i = tid; i < 128; i += NTHREADS) sbrc[i] = brc[i];
    __syncthreads();

    const int ntiles = (E + TILE_E - 1) / TILE_E;

    for (int tile = blockIdx.x * NGROUPS + grp; tile < ntiles; tile += gridDim.x * NGROUPS) {
        const int base = tile * TILE_E;
        const int n_e  = min(TILE_E, E - base);

        // ---- stage 0: X = softmax(m_i*m_j) closed form -> A0 (8 thr/edge) ----
        {
            const int e  = tg >> 3;           // edge in tile (0..15)
            const int qq = tg & 7;            // 8-feature chunk
            const int eg = base + (e < n_e ? e : n_e - 1);
            const int mrowi = omI[eg];
            const int jj    = atI[eg];
            if (qq == 0) { sObs[e] = obsI[eg]; sJ[e] = jj; }
            const float* mrow = km + (size_t)mrowi * 64;
            float mv[8];
            float s = 0.f;
            #pragma unroll
            for (int t = 0; t < 2; t++) {
                float4 v = *(const float4*)(mrow + qq * 8 + t * 4);
                mv[t*4+0]=v.x; mv[t*4+1]=v.y; mv[t*4+2]=v.z; mv[t*4+3]=v.w;
                s += v.x + v.y + v.z + v.w;
            }
            s += __shfl_xor_sync(0xffffffffu, s, 1);
            s += __shfl_xor_sync(0xffffffffu, s, 2);
            s += __shfl_xor_sync(0xffffffffu, s, 4);
            const float kn = s - mrow[jj];
            const float EU = 2.71828182845904523536f;
            const float alpha = 1.f / (kn * EU + (64.f - kn));
            const uint32_t ua = f2tf(alpha);
            const uint32_t ub = f2tf(EU * alpha);
            uint32_t w[8];
            #pragma unroll
            for (int t = 0; t < 8; t++) {
                const int f = qq * 8 + t;
                w[t] = (mv[t] != 0.f && f != jj) ? ub : ua;
            }
            uint4* dst = (uint4*)(A0 + e * STR0 + qq * 8);
            dst[0] = make_uint4(w[0], w[1], w[2], w[3]);
            dst[1] = make_uint4(w[4], w[5], w[6], w[7]);
        }
        GBAR();

        // ---- stage 1: H = gelu(X @ W1 + b1) -> A1   (K=64, N=128) ----
        {
            float acc[4][4];
            #pragma unroll
            for (int nt = 0; nt < 4; nt++)
                { acc[nt][0]=0.f; acc[nt][1]=0.f; acc[nt][2]=0.f; acc[nt][3]=0.f; }
            const uint32_t ab = A0u + ((rowoff * STR0 + coloff) << 2);
            #pragma unroll
            for (int ks = 0; ks < 8; ks++) {
                uint32_t a0, a1, a2, a3;
                ldsm4(a0, a1, a2, a3, ab + ks * 32);
                #pragma unroll
                for (int nt = 0; nt < 4; nt++) {
                    const uint2 b = __ldg((const uint2*)(W1f + (((wl*4+nt)*8+ks)<<6) + lane*2));
                    mma8(acc[nt], a0, a1, a2, a3, b.x, b.y);
                }
            }
            #pragma unroll
            for (int nt = 0; nt < 4; nt++) {
                const int n0 = (wl * 4 + nt) * 8 + 2 * q;
                const float2 bb = *(const float2*)(sb1 + n0);
                uint2 lo, hi;
                lo.x = __float_as_uint(gelu_f(acc[nt][0] + bb.x));
                lo.y = __float_as_uint(gelu_f(acc[nt][1] + bb.y));
                hi.x = __float_as_uint(gelu_f(acc[nt][2] + bb.x));
                hi.y = __float_as_uint(gelu_f(acc[nt][3] + bb.y));
                *(uint2*)(A1 + r * STR1 + n0)       = lo;
                *(uint2*)(A1 + (r + 8) * STR1 + n0) = hi;
            }
        }
        GBAR();

        // ---- stage 2: T = fea_corr[j] * gelu(H @ W2 + b2) -> A0   (K=128, N=64) ----
        {
            float acc[2][4];
            #pragma unroll
            for (int nt = 0; nt < 2; nt++)
                { acc[nt][0]=0.f; acc[nt][1]=0.f; acc[nt][2]=0.f; acc[nt][3]=0.f; }
            const uint32_t ab = A1u + ((rowoff * STR1 + coloff) << 2);
            #pragma unroll
            for (int ks = 0; ks < 16; ks++) {
                uint32_t a0, a1, a2, a3;
                ldsm4(a0, a1, a2, a3, ab + ks * 32);
                #pragma unroll
                for (int nt = 0; nt < 2; nt++) {
                    const uint2 b = __ldg((const uint2*)(W2f + (((wl*2+nt)*16+ks)<<6) + lane*2));
                    mma8(acc[nt], a0, a1, a2, a3, b.x, b.y);
                }
            }
            const int e0 = r, e1 = r + 8;
            const int j0 = sJ[e0], j1 = sJ[e1];
            #pragma unroll
            for (int nt = 0; nt < 2; nt++) {
                const int n0 = (wl * 2 + nt) * 8 + 2 * q;
                const float2 bb = *(const float2*)(sb2 + n0);
                const float2 f0 = __ldg((const float2*)(fcorr + (size_t)j0 * 64 + n0));
                const float2 f1 = __ldg((const float2*)(fcorr + (size_t)j1 * 64 + n0));
                uint2 lo, hi;
                lo.x = __float_as_uint(f0.x * gelu_f(acc[nt][0] + bb.x));
                lo.y = __float_as_uint(f0.y * gelu_f(acc[nt][1] + bb.y));
                hi.x = __float_as_uint(f1.x * gelu_f(acc[nt][2] + bb.x));
                hi.y = __float_as_uint(f1.y * gelu_f(acc[nt][3] + bb.y));
                *(uint2*)(A0 + e0 * STR0 + n0) = lo;
                *(uint2*)(A0 + e1 * STR0 + n0) = hi;
            }
        }
        GBAR();

        // ---- stage 3: U = obs_h * gelu(T @ Wrr + brr) -> A1   (K=64, N=128) ----
        {
            float acc[4][4];
            #pragma unroll
            for (int nt = 0; nt < 4; nt++)
                { acc[nt][0]=0.f; acc[nt][1]=0.f; acc[nt][2]=0.f; acc[nt][3]=0.f; }
            const uint32_t ab = A0u + ((rowoff * STR0 + coloff) << 2);
            #pragma unroll
            for (int ks = 0; ks < 8; ks++) {
                uint32_t a0, a1, a2, a3;
                ldsm4(a0, a1, a2, a3, ab + ks * 32);
                #pragma unroll
                for (int nt = 0; nt < 4; nt++) {
                    const uint2 b = __ldg((const uint2*)(Wrrf + (((wl*4+nt)*8+ks)<<6) + lane*2));
                    mma8(acc[nt], a0, a1, a2, a3, b.x, b.y);
                }
            }
            const int e0 = r, e1 = r + 8;
            const size_t o0 = (size_t)sObs[e0] * 128;
            const size_t o1 = (size_t)sObs[e1] * 128;
            #pragma unroll
            for (int nt = 0; nt < 4; nt++) {
                const int n0 = (wl * 4 + nt) * 8 + 2 * q;
                const float2 bb = *(const float2*)(sbrr + n0);
                const float2 v0 = __ldg((const float2*)(obsE + o0 + n0));
                const float2 v1 = __ldg((const float2*)(obsE + o1 + n0));
                uint2 lo, hi;
                lo.x = __float_as_uint(v0.x * gelu_f(acc[nt][0] + bb.x));
                lo.y = __float_as_uint(v0.y * gelu_f(acc[nt][1] + bb.y));
                hi.x = __float_as_uint(v1.x * gelu_f(acc[nt][2] + bb.x));
                hi.y = __float_as_uint(v1.y * gelu_f(acc[nt][3] + bb.y));
                *(uint2*)(A1 + e0 * STR1 + n0) = lo;
                *(uint2*)(A1 + e1 * STR1 + n0) = hi;
            }
        }
        GBAR();

        // ---- stage 4: out = gelu(U @ Wrc + brc) -> global   (K=128, N=128) ----
        {
            float acc[4][4];
            #pragma unroll
            for (int nt = 0; nt < 4; nt++)
                { acc[nt][0]=0.f; acc[nt][1]=0.f; acc[nt][2]=0.f; acc[nt][3]=0.f; }
            const uint32_t ab = A1u + ((rowoff * STR1 + coloff) << 2);
            #pragma unroll
            for (int ks = 0; ks < 16; ks++) {
                uint32_t a0, a1, a2, a3;
                ldsm4(a0, a1, a2, a3, ab + ks * 32);
                #pragma unroll
                for (int nt = 0; nt < 4; nt++) {
                    const uint2 b = __ldg((const uint2*)(Wrcf + (((wl*4+nt)*16+ks)<<6) + lane*2));
                    mma8(acc[nt], a0, a1, a2, a3, b.x, b.y);
                }
            }
            const int e0 = r, e1 = r + 8;
            float* o0 = out + (size_t)(base + e0) * 128;
            float* o1 = out + (size_t)(base + e1) * 128;
            #pragma unroll
            for (int nt = 0; nt < 4; nt++) {
                const int n0 = (wl * 4 + nt) * 8 + 2 * q;
                const float2 bb = *(const float2*)(sbrc + n0);
                if (e0 < n_e) {
                    float2 v;
                    v.x = gelu_f(acc[nt][0] + bb.x);
                    v.y = gelu_f(acc[nt][1] + bb.y);
                    *(float2*)(o0 + n0) = v;
                }
                if (e1 < n_e) {
                    float2 v;
                    v.x = gelu_f(acc[nt][2] + bb.x);
                    v.y = gelu_f(acc[nt][3] + bb.y);
                    *(float2*)(o1 + n0) = v;
                }
            }
        }
        GBAR();   // protects A0/sObs/sJ before next tile's stage 0
    }
}

extern "C" void kernel_launch(void* const* d_in, const int* in_sizes, int n_in,
                              void* d_out, int out_size) {
    const float* known_mask   = (const float*)d_in[0];
    const int*   obs_idx      = (const int*)  d_in[1];
    const int*   obs_mask_idx = (const int*)  d_in[2];
    const int*   attr_idx     = (const int*)  d_in[3];
    const float* obs_embs     = (const float*)d_in[4];
    const float* fea_corr     = (const float*)d_in[5];
    const float* W1  = (const float*)d_in[6];
    const float* b1  = (const float*)d_in[7];
    const float* W2  = (const float*)d_in[8];
    const float* b2  = (const float*)d_in[9];
    const float* Wrr = (const float*)d_in[10];
    const float* brr = (const float*)d_in[11];
    const float* Wrc = (const float*)d_in[12];
    const float* brc = (const float*)d_in[13];
    const int E = in_sizes[1];

    int sms = 148;
    cudaDeviceGetAttribute(&sms, cudaDevAttrMultiProcessorCount, 0);
    cudaFuncSetAttribute(attr_rel_mma,
                         cudaFuncAttributeMaxDynamicSharedMemorySize, SMEM_BYTES);

    prep_weights<<<160, 256>>>(W1, W2, Wrr, Wrc);
    attr_rel_mma<<<sms, NTHREADS, SMEM_BYTES>>>(
        known_mask, obs_idx, obs_mask_idx, attr_idx, obs_embs, fea_corr,
        b1, b2, brr, brc,
        (float*)d_out, E);
}

// round 13
// speedup vs baseline: 1.2310x; 1.2310x over previous
#include <cuda_runtime.h>
#include <math.h>
#include <stdint.h>

#define NTHREADS 384
#define NGROUPS  3
#define TILE_E   32          // edges per group-tile

// fragment-ordered tf32 weights in device-global scratch (L1/L2-cached)
// PAIR layout: per (nt, kp) block of 128 words, lane owns words [lane*4..lane*4+3]
//  = { b(2kp).x, b(2kp).y, b(2kp+1).x, b(2kp+1).y }
#define W1F_OFF   0
#define W2F_OFF   8192
#define WRRF_OFF  16384
#define WRCF_OFF  24576
__device__ __align__(16) uint32_t g_Wf[40960];

// ---------------- smem layout (bytes): activations only ----------------
#define OFF_A0    0                       // 3 x (32 x 68 f)  = 26112
#define OFF_A1    26112                   // 3 x (32 x 132 f) = 50688
#define OFF_B1    76800                   // 128 f
#define OFF_B2    77312                   // 64 f
#define OFF_BRR   77568                   // 128 f
#define OFF_BRC   78080                   // 128 f
#define OFF_OBS   78592                   // 3 x 32 int
#define OFF_J     78976                   // 3 x 32 int
#define SMEM_BYTES 79360

#define STR0 68    // word stride, A0: rows 4 banks apart -> LDSM conflict-free
#define STR1 132   // word stride, A1

// tanh-based GELU via MUFU.TANH (base sm_75+ feature).
// gelu(x) = 0.5x * (1 + tanh(sqrt(2/pi) * (x + 0.044715 x^3)))
__device__ __forceinline__ float gelu_f(float x) {
    const float k0 = 0.7978845608028654f;
    const float k1 = 0.0356774081f;       // 0.044715 * sqrt(2/pi)
    const float x2 = x * x;
    const float u  = x * fmaf(k1, x2, k0);
    float th;
    asm("tanh.approx.f32 %0, %1;" : "=f"(th) : "f"(u));
    const float hx = 0.5f * x;
    return fmaf(hx, th, hx);
}

__device__ __forceinline__ uint32_t f2tf(float x) {
    uint32_t r;
    asm("cvt.rna.tf32.f32 %0, %1;" : "=r"(r) : "f"(x));
    return r;
}

__device__ __forceinline__ void mma8(float d[4], uint32_t a0, uint32_t a1,
                                     uint32_t a2, uint32_t a3,
                                     uint32_t b0, uint32_t b1) {
    asm volatile(
        "mma.sync.aligned.m16n8k8.row.col.f32.tf32.tf32.f32 "
        "{%0,%1,%2,%3}, {%4,%5,%6,%7}, {%8,%9}, {%0,%1,%2,%3};"
        : "+f"(d[0]), "+f"(d[1]), "+f"(d[2]), "+f"(d[3])
        : "r"(a0), "r"(a1), "r"(a2), "r"(a3), "r"(b0), "r"(b1));
}

__device__ __forceinline__ void ldsm4(uint32_t& a0, uint32_t& a1,
                                      uint32_t& a2, uint32_t& a3, uint32_t addr) {
    asm volatile("ldmatrix.sync.aligned.m8n8.x4.shared.b16 {%0,%1,%2,%3}, [%4];"
                 : "=r"(a0), "=r"(a1), "=r"(a2), "=r"(a3) : "r"(addr));
}

#define GBAR() asm volatile("bar.sync %0, 128;" :: "r"(grp + 1) : "memory")

// one element of W [K,N] row-major -> tf32 B-fragment PAIR order
__device__ __forceinline__ void pf1(const float* __restrict__ W, int K, int N,
                                    uint32_t* __restrict__ dst, int j) {
    const int P    = K >> 4;          // k-step pairs
    const int w    = j & 3;
    const int lane = (j >> 2) & 31;
    const int fp   = j >> 7;
    const int p    = fp % P;
    const int nt   = fp / P;
    const int ks   = 2 * p + (w >> 1);
    const int reg  = w & 1;
    const int k = ks * 8 + (lane & 3) + reg * 4;
    const int n = nt * 8 + (lane >> 2);
    dst[j] = f2tf(W[k * N + n]);
}

__global__ void prep_weights(const float* __restrict__ W1, const float* __restrict__ W2,
                             const float* __restrict__ Wrr, const float* __restrict__ Wrc) {
    int i = blockIdx.x * blockDim.x + threadIdx.x;
    for (; i < 40960; i += gridDim.x * blockDim.x) {
        if (i < 8192)       pf1(W1,   64, 128, g_Wf + W1F_OFF,  i);
        else if (i < 16384) pf1(W2,  128,  64, g_Wf + W2F_OFF,  i - 8192);
        else if (i < 24576) pf1(Wrr,  64, 128, g_Wf + WRRF_OFF, i - 16384);
        else                pf1(Wrc, 128, 128, g_Wf + WRCF_OFF, i - 24576);
    }
}

__global__ void __launch_bounds__(NTHREADS, 1)
attr_rel_mma(const float* __restrict__ km,  const int* __restrict__ obsI,
             const int* __restrict__ omI,   const int* __restrict__ atI,
             const float* __restrict__ obsE, const float* __restrict__ fcorr,
             const float* __restrict__ b1,  const float* __restrict__ b2,
             const float* __restrict__ brr, const float* __restrict__ brc,
             float* __restrict__ out, int E)
{
    extern __shared__ char smem[];
    float* sb1  = (float*)(smem + OFF_B1);
    float* sb2  = (float*)(smem + OFF_B2);
    float* sbrr = (float*)(smem + OFF_BRR);
    float* sbrc = (float*)(smem + OFF_BRC);

    const int tid  = threadIdx.x;
    const int warp = tid >> 5;
    const int lane = tid & 31;
    const int grp  = warp >> 2;          // work-group 0..2
    const int wl   = warp & 3;           // N-group within work-group
    const int tg   = tid & 127;          // thread id within group
    const int r    = lane >> 2;
    const int q    = lane & 3;

    uint32_t* A0 = (uint32_t*)(smem + OFF_A0) + grp * (TILE_E * STR0);
    uint32_t* A1 = (uint32_t*)(smem + OFF_A1) + grp * (TILE_E * STR1);
    int* sObs = (int*)(smem + OFF_OBS) + grp * TILE_E;
    int* sJ   = (int*)(smem + OFF_J)   + grp * TILE_E;

    const uint32_t A0u = (uint32_t)__cvta_generic_to_shared(A0);
    const uint32_t A1u = (uint32_t)__cvta_generic_to_shared(A1);
    const int rowoff = (lane & 7) + ((lane >> 3) & 1) * 8;
    const int coloff = (lane >> 4) << 2;

    const uint32_t* W1f  = g_Wf + W1F_OFF;
    const uint32_t* W2f  = g_Wf + W2F_OFF;
    const uint32_t* Wrrf = g_Wf + WRRF_OFF;
    const uint32_t* Wrcf = g_Wf + WRCF_OFF;

    for (int i = tid; i < 128; i += NTHREADS) sb1[i]  = b1[i];
    for (int i = tid; i < 64;  i += NTHREADS) sb2[i]  = b2[i];
    for (int i = tid; i < 128; i += NTHREADS) sbrr[i] = brr[i];
    for (int i = tid; i < 128; i += NTHREADS) sbrc[i] = brc[i];
    __syncthreads();

    const int ntiles = (E + TILE_E - 1) / TILE_E;

    for (int tile = blockIdx.x * NGROUPS + grp; tile < ntiles; tile += gridDim.x * NGROUPS) {
        const int base = tile * TILE_E;
        const int n_e  = min(TILE_E, E - base);

        // ---- stage 0: X = softmax(m_i*m_j) closed form -> A0 ----
        {
            const int e  = tg >> 2;
            const int qq = tg & 3;
            const int eg = base + (e < n_e ? e : n_e - 1);
            const int mrowi = omI[eg];
            const int jj    = atI[eg];
            if (qq == 0) { sObs[e] = obsI[eg]; sJ[e] = jj; }
            const float* mrow = km + (size_t)mrowi * 64;
            float mv[16];
            float s = 0.f;
            #pragma unroll
            for (int t = 0; t < 4; t++) {
                float4 v = *(const float4*)(mrow + qq * 16 + t * 4);
                mv[t*4+0]=v.x; mv[t*4+1]=v.y; mv[t*4+2]=v.z; mv[t*4+3]=v.w;
                s += v.x + v.y + v.z + v.w;
            }
            s += __shfl_xor_sync(0xffffffffu, s, 1);
            s += __shfl_xor_sync(0xffffffffu, s, 2);
            const float kn = s - mrow[jj];
            const float EU = 2.71828182845904523536f;
            const float alpha = 1.f / (kn * EU + (64.f - kn));
            const uint32_t ua = f2tf(alpha);
            const uint32_t ub = f2tf(EU * alpha);
            uint32_t w[16];
            #pragma unroll
            for (int t = 0; t < 16; t++) {
                const int f = qq * 16 + t;
                w[t] = (mv[t] != 0.f && f != jj) ? ub : ua;
            }
            uint4* dst = (uint4*)(A0 + e * STR0 + qq * 16);
            dst[0] = make_uint4(w[0],  w[1],  w[2],  w[3]);
            dst[1] = make_uint4(w[4],  w[5],  w[6],  w[7]);
            dst[2] = make_uint4(w[8],  w[9],  w[10], w[11]);
            dst[3] = make_uint4(w[12], w[13], w[14], w[15]);
        }
        GBAR();

        // ---- stage 1: H = gelu(X @ W1 + b1) -> A1   (K=64, N=128) ----
        {
            float acc[2][4][4];
            #pragma unroll
            for (int m = 0; m < 2; m++)
                #pragma unroll
                for (int nt = 0; nt < 4; nt++)
                    { acc[m][nt][0]=0.f; acc[m][nt][1]=0.f; acc[m][nt][2]=0.f; acc[m][nt][3]=0.f; }
            #pragma unroll
            for (int m = 0; m < 2; m++) {
                const uint32_t ab = A0u + (((m * 16 + rowoff) * STR0 + coloff) << 2);
                #pragma unroll
                for (int kp = 0; kp < 4; kp++) {
                    uint32_t a0, a1, a2, a3, c0, c1, c2, c3;
                    ldsm4(a0, a1, a2, a3, ab + kp * 64);
                    ldsm4(c0, c1, c2, c3, ab + kp * 64 + 32);
                    #pragma unroll
                    for (int nt = 0; nt < 4; nt++) {
                        const uint4 b = __ldg((const uint4*)(W1f + (((wl*4+nt)*4+kp)<<7) + lane*4));
                        mma8(acc[m][nt], a0, a1, a2, a3, b.x, b.y);
                        mma8(acc[m][nt], c0, c1, c2, c3, b.z, b.w);
                    }
                }
            }
            #pragma unroll
            for (int m = 0; m < 2; m++) {
                const int e0 = m * 16 + r;
                #pragma unroll
                for (int nt = 0; nt < 4; nt++) {
                    const int n0 = (wl * 4 + nt) * 8 + 2 * q;
                    const float2 bb = *(const float2*)(sb1 + n0);
                    uint2 lo, hi;
                    lo.x = __float_as_uint(gelu_f(acc[m][nt][0] + bb.x));
                    lo.y = __float_as_uint(gelu_f(acc[m][nt][1] + bb.y));
                    hi.x = __float_as_uint(gelu_f(acc[m][nt][2] + bb.x));
                    hi.y = __float_as_uint(gelu_f(acc[m][nt][3] + bb.y));
                    *(uint2*)(A1 + e0 * STR1 + n0)       = lo;
                    *(uint2*)(A1 + (e0 + 8) * STR1 + n0) = hi;
                }
            }
        }
        GBAR();

        // ---- stage 2: T = fea_corr[j] * gelu(H @ W2 + b2) -> A0   (K=128, N=64) ----
        {
            float acc[2][2][4];
            #pragma unroll
            for (int m = 0; m < 2; m++)
                #pragma unroll
                for (int nt = 0; nt < 2; nt++)
                    { acc[m][nt][0]=0.f; acc[m][nt][1]=0.f; acc[m][nt][2]=0.f; acc[m][nt][3]=0.f; }
            #pragma unroll
            for (int m = 0; m < 2; m++) {
                const uint32_t ab = A1u + (((m * 16 + rowoff) * STR1 + coloff) << 2);
                #pragma unroll
                for (int kp = 0; kp < 8; kp++) {
                    uint32_t a0, a1, a2, a3, c0, c1, c2, c3;
                    ldsm4(a0, a1, a2, a3, ab + kp * 64);
                    ldsm4(c0, c1, c2, c3, ab + kp * 64 + 32);
                    #pragma unroll
                    for (int nt = 0; nt < 2; nt++) {
                        const uint4 b = __ldg((const uint4*)(W2f + (((wl*2+nt)*8+kp)<<7) + lane*4));
                        mma8(acc[m][nt], a0, a1, a2, a3, b.x, b.y);
                        mma8(acc[m][nt], c0, c1, c2, c3, b.z, b.w);
                    }
                }
            }
            #pragma unroll
            for (int m = 0; m < 2; m++) {
                const int e0 = m * 16 + r, e1 = e0 + 8;
                const int j0 = sJ[e0], j1 = sJ[e1];
                #pragma unroll
                for (int nt = 0; nt < 2; nt++) {
                    const int n0 = (wl * 2 + nt) * 8 + 2 * q;
                    const float2 bb = *(const float2*)(sb2 + n0);
                    const float2 f0 = __ldg((const float2*)(fcorr + (size_t)j0 * 64 + n0));
                    const float2 f1 = __ldg((const float2*)(fcorr + (size_t)j1 * 64 + n0));
                    uint2 lo, hi;
                    lo.x = __float_as_uint(f0.x * gelu_f(acc[m][nt][0] + bb.x));
                    lo.y = __float_as_uint(f0.y * gelu_f(acc[m][nt][1] + bb.y));
                    hi.x = __float_as_uint(f1.x * gelu_f(acc[m][nt][2] + bb.x));
                    hi.y = __float_as_uint(f1.y * gelu_f(acc[m][nt][3] + bb.y));
                    *(uint2*)(A0 + e0 * STR0 + n0) = lo;
                    *(uint2*)(A0 + e1 * STR0 + n0) = hi;
                }
            }
        }
        GBAR();

        // ---- stage 3: U = obs_h * gelu(T @ Wrr + brr) -> A1   (K=64, N=128) ----
        {
            float acc[2][4][4];
            #pragma unroll
            for (int m = 0; m < 2; m++)
                #pragma unroll
                for (int nt = 0; nt < 4; nt++)
                    { acc[m][nt][0]=0.f; acc[m][nt][1]=0.f; acc[m][nt][2]=0.f; acc[m][nt][3]=0.f; }
            #pragma unroll
            for (int m = 0; m < 2; m++) {
                const uint32_t ab = A0u + (((m * 16 + rowoff) * STR0 + coloff) << 2);
                #pragma unroll
                for (int kp = 0; kp < 4; kp++) {
                    uint32_t a0, a1, a2, a3, c0, c1, c2, c3;
                    ldsm4(a0, a1, a2, a3, ab + kp * 64);
                    ldsm4(c0, c1, c2, c3, ab + kp * 64 + 32);
                    #pragma unroll
                    for (int nt = 0; nt < 4; nt++) {
                        const uint4 b = __ldg((const uint4*)(Wrrf + (((wl*4+nt)*4+kp)<<7) + lane*4));
                        mma8(acc[m][nt], a0, a1, a2, a3, b.x, b.y);
                        mma8(acc[m][nt], c0, c1, c2, c3, b.z, b.w);
                    }
                }
            }
            #pragma unroll
            for (int m = 0; m < 2; m++) {
                const int e0 = m * 16 + r, e1 = e0 + 8;
                const size_t o0 = (size_t)sObs[e0] * 128;
                const size_t o1 = (size_t)sObs[e1] * 128;
                #pragma unroll
                for (int nt = 0; nt < 4; nt++) {
                    const int n0 = (wl * 4 + nt) * 8 + 2 * q;
                    const float2 bb = *(const float2*)(sbrr + n0);
                    const float2 v0 = __ldg((const float2*)(obsE + o0 + n0));
                    const float2 v1 = __ldg((const float2*)(obsE + o1 + n0));
                    uint2 lo, hi;
                    lo.x = __float_as_uint(v0.x * gelu_f(acc[m][nt][0] + bb.x));
                    lo.y = __float_as_uint(v0.y * gelu_f(acc[m][nt][1] + bb.y));
                    hi.x = __float_as_uint(v1.x * gelu_f(acc[m][nt][2] + bb.x));
                    hi.y = __float_as_uint(v1.y * gelu_f(acc[m][nt][3] + bb.y));
                    *(uint2*)(A1 + e0 * STR1 + n0) = lo;
                    *(uint2*)(A1 + e1 * STR1 + n0) = hi;
                }
            }
        }
        GBAR();

        // ---- stage 4: out = gelu(U @ Wrc + brc) -> global   (K=128, N=128) ----
        {
            float acc[2][4][4];
            #pragma unroll
            for (int m = 0; m < 2; m++)
                #pragma unroll
                for (int nt = 0; nt < 4; nt++)
                    { acc[m][nt][0]=0.f; acc[m][nt][1]=0.f; acc[m][nt][2]=0.f; acc[m][nt][3]=0.f; }
            #pragma unroll
            for (int m = 0; m < 2; m++) {
                const uint32_t ab = A1u + (((m * 16 + rowoff) * STR1 + coloff) << 2);
                #pragma unroll
                for (int kp = 0; kp < 8; kp++) {
                    uint32_t a0, a1, a2, a3, c0, c1, c2, c3;
                    ldsm4(a0, a1, a2, a3, ab + kp * 64);
                    ldsm4(c0, c1, c2, c3, ab + kp * 64 + 32);
                    #pragma unroll
                    for (int nt = 0; nt < 4; nt++) {
                        const uint4 b = __ldg((const uint4*)(Wrcf + (((wl*4+nt)*8+kp)<<7) + lane*4));
                        mma8(acc[m][nt], a0, a1, a2, a3, b.x, b.y);
                        mma8(acc[m][nt], c0, c1, c2, c3, b.z, b.w);
                    }
                }
            }
            #pragma unroll
            for (int m = 0; m < 2; m++) {
                const int e0 = m * 16 + r, e1 = e0 + 8;
                float* o0 = out + (size_t)(base + e0) * 128;
                float* o1 = out + (size_t)(base + e1) * 128;
                #pragma unroll
                for (int nt = 0; nt < 4; nt++) {
                    const int n0 = (wl * 4 + nt) * 8 + 2 * q;
                    const float2 bb = *(const float2*)(sbrc + n0);
                    if (e0 < n_e) {
                        float2 v;
                        v.x = gelu_f(acc[m][nt][0] + bb.x);
                        v.y = gelu_f(acc[m][nt][1] + bb.y);
                        *(float2*)(o0 + n0) = v;
                    }
                    if (e1 < n_e) {
                        float2 v;
                        v.x = gelu_f(acc[m][nt][2] + bb.x);
                        v.y = gelu_f(acc[m][nt][3] + bb.y);
                        *(float2*)(o1 + n0) = v;
                    }
                }
            }
        }
        GBAR();   // protects A0/sObs/sJ before next tile's stage 0
    }
}

extern "C" void kernel_launch(void* const* d_in, const int* in_sizes, int n_in,
                              void* d_out, int out_size) {
    const float* known_mask   = (const float*)d_in[0];
    const int*   obs_idx      = (const int*)  d_in[1];
    const int*   obs_mask_idx = (const int*)  d_in[2];
    const int*   attr_idx     = (const int*)  d_in[3];
    const float* obs_embs     = (const float*)d_in[4];
    const float* fea_corr     = (const float*)d_in[5];
    const float* W1  = (const float*)d_in[6];
    const float* b1  = (const float*)d_in[7];
    const float* W2  = (const float*)d_in[8];
    const float* b2  = (const float*)d_in[9];
    const float* Wrr = (const float*)d_in[10];
    const float* brr = (const float*)d_in[11];
    const float* Wrc = (const float*)d_in[12];
    const float* brc = (const float*)d_in[13];
    const int E = in_sizes[1];

    int sms = 148;
    cudaDeviceGetAttribute(&sms, cudaDevAttrMultiProcessorCount, 0);
    cudaFuncSetAttribute(attr_rel_mma,
                         cudaFuncAttributeMaxDynamicSharedMemorySize, SMEM_BYTES);

    prep_weights<<<160, 256>>>(W1, W2, Wrr, Wrc);
    attr_rel_mma<<<sms, NTHREADS, SMEM_BYTES>>>(
        known_mask, obs_idx, obs_mask_idx, attr_idx, obs_embs, fea_corr,
        b1, b2, brr, brc,
        (float*)d_out, E);
}

// round 14
// speedup vs baseline: 1.2363x; 1.0043x over previous
#include <cuda_runtime.h>
#include <math.h>
#include <stdint.h>

#define NTHREADS 384
#define NGROUPS  3
#define TILE_E   32          // edges per group-tile

// fragment-ordered tf32 weights in device-global scratch (L1/L2-cached)
// PAIR layout: per (nt, kp) block of 128 words, lane owns words [lane*4..lane*4+3]
#define W1F_OFF   0
#define W2F_OFF   8192
#define WRRF_OFF  16384
#define WRCF_OFF  24576
__device__ __align__(16) uint32_t g_Wf[40960];

// ---------------- smem layout (bytes): activations only ----------------
#define OFF_A0    0                       // 3 x (32 x 68 f)  = 26112
#define OFF_A1    26112                   // 3 x (32 x 132 f) = 50688
#define OFF_B1    76800                   // 128 f
#define OFF_B2    77312                   // 64 f
#define OFF_BRR   77568                   // 128 f
#define OFF_BRC   78080                   // 128 f
#define OFF_OBS   78592                   // 3 x 32 int
#define OFF_J     78976                   // 3 x 32 int
#define SMEM_BYTES 79360

#define STR0 68    // word stride, A0: rows 4 banks apart -> LDSM conflict-free
#define STR1 132   // word stride, A1

// tanh-based GELU via MUFU.TANH
__device__ __forceinline__ float gelu_f(float x) {
    const float k0 = 0.7978845608028654f;
    const float k1 = 0.0356774081f;       // 0.044715 * sqrt(2/pi)
    const float x2 = x * x;
    const float u  = x * fmaf(k1, x2, k0);
    float th;
    asm("tanh.approx.f32 %0, %1;" : "=f"(th) : "f"(u));
    const float hx = 0.5f * x;
    return fmaf(hx, th, hx);
}

__device__ __forceinline__ uint32_t f2tf(float x) {
    uint32_t r;
    asm("cvt.rna.tf32.f32 %0, %1;" : "=r"(r) : "f"(x));
    return r;
}

__device__ __forceinline__ void mma8(float d[4], uint32_t a0, uint32_t a1,
                                     uint32_t a2, uint32_t a3,
                                     uint32_t b0, uint32_t b1) {
    asm volatile(
        "mma.sync.aligned.m16n8k8.row.col.f32.tf32.tf32.f32 "
        "{%0,%1,%2,%3}, {%4,%5,%6,%7}, {%8,%9}, {%0,%1,%2,%3};"
        : "+f"(d[0]), "+f"(d[1]), "+f"(d[2]), "+f"(d[3])
        : "r"(a0), "r"(a1), "r"(a2), "r"(a3), "r"(b0), "r"(b1));
}

__device__ __forceinline__ void ldsm4(uint32_t& a0, uint32_t& a1,
                                      uint32_t& a2, uint32_t& a3, uint32_t addr) {
    asm volatile("ldmatrix.sync.aligned.m8n8.x4.shared.b16 {%0,%1,%2,%3}, [%4];"
                 : "=r"(a0), "=r"(a1), "=r"(a2), "=r"(a3) : "r"(addr));
}

#define GBAR() asm volatile("bar.sync %0, 128;" :: "r"(grp + 1) : "memory")

// one element of W [K,N] row-major -> tf32 B-fragment PAIR order
__device__ __forceinline__ void pf1(const float* __restrict__ W, int K, int N,
                                    uint32_t* __restrict__ dst, int j) {
    const int P    = K >> 4;          // k-step pairs
    const int w    = j & 3;
    const int lane = (j >> 2) & 31;
    const int fp   = j >> 7;
    const int p    = fp % P;
    const int nt   = fp / P;
    const int ks   = 2 * p + (w >> 1);
    const int reg  = w & 1;
    const int k = ks * 8 + (lane & 3) + reg * 4;
    const int n = nt * 8 + (lane >> 2);
    dst[j] = f2tf(W[k * N + n]);
}

__global__ void prep_weights(const float* __restrict__ W1, const float* __restrict__ W2,
                             const float* __restrict__ Wrr, const float* __restrict__ Wrc) {
    int i = blockIdx.x * blockDim.x + threadIdx.x;
    for (; i < 40960; i += gridDim.x * blockDim.x) {
        if (i < 8192)       pf1(W1,   64, 128, g_Wf + W1F_OFF,  i);
        else if (i < 16384) pf1(W2,  128,  64, g_Wf + W2F_OFF,  i - 8192);
        else if (i < 24576) pf1(Wrr,  64, 128, g_Wf + WRRF_OFF, i - 16384);
        else                pf1(Wrc, 128, 128, g_Wf + WRCF_OFF, i - 24576);
    }
}

__global__ void __launch_bounds__(NTHREADS, 1)
attr_rel_mma(const float* __restrict__ km,  const int* __restrict__ obsI,
             const int* __restrict__ omI,   const int* __restrict__ atI,
             const float* __restrict__ obsE, const float* __restrict__ fcorr,
             const float* __restrict__ b1,  const float* __restrict__ b2,
             const float* __restrict__ brr, const float* __restrict__ brc,
             float* __restrict__ out, int E)
{
    extern __shared__ char smem[];
    float* sb1  = (float*)(smem + OFF_B1);
    float* sb2  = (float*)(smem + OFF_B2);
    float* sbrr = (float*)(smem + OFF_BRR);
    float* sbrc = (float*)(smem + OFF_BRC);

    const int tid  = threadIdx.x;
    const int warp = tid >> 5;
    const int lane = tid & 31;
    const int grp  = warp >> 2;          // work-group 0..2
    const int wl   = warp & 3;           // N-group within work-group
    const int tg   = tid & 127;          // thread id within group
    const int r    = lane >> 2;
    const int q    = lane & 3;

    uint32_t* A0 = (uint32_t*)(smem + OFF_A0) + grp * (TILE_E * STR0);
    uint32_t* A1 = (uint32_t*)(smem + OFF_A1) + grp * (TILE_E * STR1);
    int* sObs = (int*)(smem + OFF_OBS) + grp * TILE_E;
    int* sJ   = (int*)(smem + OFF_J)   + grp * TILE_E;

    const uint32_t A0u = (uint32_t)__cvta_generic_to_shared(A0);
    const uint32_t A1u = (uint32_t)__cvta_generic_to_shared(A1);
    const int rowoff = (lane & 7) + ((lane >> 3) & 1) * 8;
    const int coloff = (lane >> 4) << 2;

    const uint32_t* W1f  = g_Wf + W1F_OFF;
    const uint32_t* W2f  = g_Wf + W2F_OFF;
    const uint32_t* Wrrf = g_Wf + WRRF_OFF;
    const uint32_t* Wrcf = g_Wf + WRCF_OFF;

    for (int i = tid; i < 128; i += NTHREADS) sb1[i]  = b1[i];
    for (int i = tid; i < 64;  i += NTHREADS) sb2[i]  = b2[i];
    for (int i = tid; i < 128; i += NTHREADS) sbrr[i] = brr[i];
    for (int i = tid; i < 128; i += NTHREADS) sbrc[i] = brc[i];
    __syncthreads();

    const int ntiles = (E + TILE_E - 1) / TILE_E;

    for (int tile = blockIdx.x * NGROUPS + grp; tile < ntiles; tile += gridDim.x * NGROUPS) {
        const int base = tile * TILE_E;
        const int n_e  = min(TILE_E, E - base);

        // ---- stage 0: X = softmax(m_i*m_j) closed form -> A0 ----
        {
            const int e  = tg >> 2;
            const int qq = tg & 3;
            const int eg = base + (e < n_e ? e : n_e - 1);
            const int mrowi = omI[eg];
            const int jj    = atI[eg];
            if (qq == 0) { sObs[e] = obsI[eg]; sJ[e] = jj; }
            const float* mrow = km + (size_t)mrowi * 64;
            float mv[16];
            float s = 0.f;
            #pragma unroll
            for (int t = 0; t < 4; t++) {
                float4 v = *(const float4*)(mrow + qq * 16 + t * 4);
                mv[t*4+0]=v.x; mv[t*4+1]=v.y; mv[t*4+2]=v.z; mv[t*4+3]=v.w;
                s += v.x + v.y + v.z + v.w;
            }
            s += __shfl_xor_sync(0xffffffffu, s, 1);
            s += __shfl_xor_sync(0xffffffffu, s, 2);
            const float kn = s - mrow[jj];
            const float EU = 2.71828182845904523536f;
            const float alpha = 1.f / (kn * EU + (64.f - kn));
            const uint32_t ua = f2tf(alpha);
            const uint32_t ub = f2tf(EU * alpha);
            uint32_t w[16];
            #pragma unroll
            for (int t = 0; t < 16; t++) {
                const int f = qq * 16 + t;
                w[t] = (mv[t] != 0.f && f != jj) ? ub : ua;
            }
            uint4* dst = (uint4*)(A0 + e * STR0 + qq * 16);
            dst[0] = make_uint4(w[0],  w[1],  w[2],  w[3]);
            dst[1] = make_uint4(w[4],  w[5],  w[6],  w[7]);
            dst[2] = make_uint4(w[8],  w[9],  w[10], w[11]);
            dst[3] = make_uint4(w[12], w[13], w[14], w[15]);
        }
        GBAR();

        // ---- stage 1: H = gelu(X @ W1 + b1) -> A1   (K=64, N=128) ----
        {
            float acc[2][4][4];
            #pragma unroll
            for (int m = 0; m < 2; m++)
                #pragma unroll
                for (int nt = 0; nt < 4; nt++)
                    { acc[m][nt][0]=0.f; acc[m][nt][1]=0.f; acc[m][nt][2]=0.f; acc[m][nt][3]=0.f; }
            const uint32_t ab0 = A0u + ((rowoff * STR0 + coloff) << 2);
            const uint32_t ab1 = A0u + (((16 + rowoff) * STR0 + coloff) << 2);
            #pragma unroll
            for (int kp = 0; kp < 4; kp++) {
                uint32_t a0,a1,a2,a3, c0,c1,c2,c3, d0,d1,d2,d3, e0_,e1_,e2_,e3_;
                ldsm4(a0, a1, a2, a3, ab0 + kp * 64);
                ldsm4(c0, c1, c2, c3, ab0 + kp * 64 + 32);
                ldsm4(d0, d1, d2, d3, ab1 + kp * 64);
                ldsm4(e0_, e1_, e2_, e3_, ab1 + kp * 64 + 32);
                #pragma unroll
                for (int nt = 0; nt < 4; nt++) {
                    const uint4 b = __ldg((const uint4*)(W1f + (((wl*4+nt)*4+kp)<<7) + lane*4));
                    mma8(acc[0][nt], a0, a1, a2, a3, b.x, b.y);
                    mma8(acc[0][nt], c0, c1, c2, c3, b.z, b.w);
                    mma8(acc[1][nt], d0, d1, d2, d3, b.x, b.y);
                    mma8(acc[1][nt], e0_, e1_, e2_, e3_, b.z, b.w);
                }
            }
            #pragma unroll
            for (int m = 0; m < 2; m++) {
                const int e0 = m * 16 + r;
                #pragma unroll
                for (int nt = 0; nt < 4; nt++) {
                    const int n0 = (wl * 4 + nt) * 8 + 2 * q;
                    const float2 bb = *(const float2*)(sb1 + n0);
                    uint2 lo, hi;
                    lo.x = __float_as_uint(gelu_f(acc[m][nt][0] + bb.x));
                    lo.y = __float_as_uint(gelu_f(acc[m][nt][1] + bb.y));
                    hi.x = __float_as_uint(gelu_f(acc[m][nt][2] + bb.x));
                    hi.y = __float_as_uint(gelu_f(acc[m][nt][3] + bb.y));
                    *(uint2*)(A1 + e0 * STR1 + n0)       = lo;
                    *(uint2*)(A1 + (e0 + 8) * STR1 + n0) = hi;
                }
            }
        }
        GBAR();

        // ---- stage 2: T = fea_corr[j] * gelu(H @ W2 + b2) -> A0   (K=128, N=64) ----
        {
            float acc[2][2][4];
            #pragma unroll
            for (int m = 0; m < 2; m++)
                #pragma unroll
                for (int nt = 0; nt < 2; nt++)
                    { acc[m][nt][0]=0.f; acc[m][nt][1]=0.f; acc[m][nt][2]=0.f; acc[m][nt][3]=0.f; }
            const uint32_t ab0 = A1u + ((rowoff * STR1 + coloff) << 2);
            const uint32_t ab1 = A1u + (((16 + rowoff) * STR1 + coloff) << 2);
            #pragma unroll
            for (int kp = 0; kp < 8; kp++) {
                uint32_t a0,a1,a2,a3, c0,c1,c2,c3, d0,d1,d2,d3, e0_,e1_,e2_,e3_;
                ldsm4(a0, a1, a2, a3, ab0 + kp * 64);
                ldsm4(c0, c1, c2, c3, ab0 + kp * 64 + 32);
                ldsm4(d0, d1, d2, d3, ab1 + kp * 64);
                ldsm4(e0_, e1_, e2_, e3_, ab1 + kp * 64 + 32);
                #pragma unroll
                for (int nt = 0; nt < 2; nt++) {
                    const uint4 b = __ldg((const uint4*)(W2f + (((wl*2+nt)*8+kp)<<7) + lane*4));
                    mma8(acc[0][nt], a0, a1, a2, a3, b.x, b.y);
                    mma8(acc[0][nt], c0, c1, c2, c3, b.z, b.w);
                    mma8(acc[1][nt], d0, d1, d2, d3, b.x, b.y);
                    mma8(acc[1][nt], e0_, e1_, e2_, e3_, b.z, b.w);
                }
            }
            #pragma unroll
            for (int m = 0; m < 2; m++) {
                const int e0 = m * 16 + r, e1 = e0 + 8;
                const int j0 = sJ[e0], j1 = sJ[e1];
                #pragma unroll
                for (int nt = 0; nt < 2; nt++) {
                    const int n0 = (wl * 2 + nt) * 8 + 2 * q;
                    const float2 bb = *(const float2*)(sb2 + n0);
                    const float2 f0 = __ldg((const float2*)(fcorr + (size_t)j0 * 64 + n0));
                    const float2 f1 = __ldg((const float2*)(fcorr + (size_t)j1 * 64 + n0));
                    uint2 lo, hi;
                    lo.x = __float_as_uint(f0.x * gelu_f(acc[m][nt][0] + bb.x));
                    lo.y = __float_as_uint(f0.y * gelu_f(acc[m][nt][1] + bb.y));
                    hi.x = __float_as_uint(f1.x * gelu_f(acc[m][nt][2] + bb.x));
                    hi.y = __float_as_uint(f1.y * gelu_f(acc[m][nt][3] + bb.y));
                    *(uint2*)(A0 + e0 * STR0 + n0) = lo;
                    *(uint2*)(A0 + e1 * STR0 + n0) = hi;
                }
            }
        }
        GBAR();

        // ---- stage 3: U = obs_h * gelu(T @ Wrr + brr) -> A1   (K=64, N=128) ----
        {
            float acc[2][4][4];
            #pragma unroll
            for (int m = 0; m < 2; m++)
                #pragma unroll
                for (int nt = 0; nt < 4; nt++)
                    { acc[m][nt][0]=0.f; acc[m][nt][1]=0.f; acc[m][nt][2]=0.f; acc[m][nt][3]=0.f; }
            const uint32_t ab0 = A0u + ((rowoff * STR0 + coloff) << 2);
            const uint32_t ab1 = A0u + (((16 + rowoff) * STR0 + coloff) << 2);
            #pragma unroll
            for (int kp = 0; kp < 4; kp++) {
                uint32_t a0,a1,a2,a3, c0,c1,c2,c3, d0,d1,d2,d3, e0_,e1_,e2_,e3_;
                ldsm4(a0, a1, a2, a3, ab0 + kp * 64);
                ldsm4(c0, c1, c2, c3, ab0 + kp * 64 + 32);
                ldsm4(d0, d1, d2, d3, ab1 + kp * 64);
                ldsm4(e0_, e1_, e2_, e3_, ab1 + kp * 64 + 32);
                #pragma unroll
                for (int nt = 0; nt < 4; nt++) {
                    const uint4 b = __ldg((const uint4*)(Wrrf + (((wl*4+nt)*4+kp)<<7) + lane*4));
                    mma8(acc[0][nt], a0, a1, a2, a3, b.x, b.y);
                    mma8(acc[0][nt], c0, c1, c2, c3, b.z, b.w);
                    mma8(acc[1][nt], d0, d1, d2, d3, b.x, b.y);
                    mma8(acc[1][nt], e0_, e1_, e2_, e3_, b.z, b.w);
                }
            }
            #pragma unroll
            for (int m = 0; m < 2; m++) {
                const int e0 = m * 16 + r, e1 = e0 + 8;
                const size_t o0 = (size_t)sObs[e0] * 128;
                const size_t o1 = (size_t)sObs[e1] * 128;
                #pragma unroll
                for (int nt = 0; nt < 4; nt++) {
                    const int n0 = (wl * 4 + nt) * 8 + 2 * q;
                    const float2 bb = *(const float2*)(sbrr + n0);
                    const float2 v0 = __ldg((const float2*)(obsE + o0 + n0));
                    const float2 v1 = __ldg((const float2*)(obsE + o1 + n0));
                    uint2 lo, hi;
                    lo.x = __float_as_uint(v0.x * gelu_f(acc[m][nt][0] + bb.x));
                    lo.y = __float_as_uint(v0.y * gelu_f(acc[m][nt][1] + bb.y));
                    hi.x = __float_as_uint(v1.x * gelu_f(acc[m][nt][2] + bb.x));
                    hi.y = __float_as_uint(v1.y * gelu_f(acc[m][nt][3] + bb.y));
                    *(uint2*)(A1 + e0 * STR1 + n0) = lo;
                    *(uint2*)(A1 + e1 * STR1 + n0) = hi;
                }
            }
        }
        GBAR();

        // ---- stage 4: out = gelu(U @ Wrc + brc) -> global   (K=128, N=128) ----
        {
            float acc[2][4][4];
            #pragma unroll
            for (int m = 0; m < 2; m++)
                #pragma unroll
                for (int nt = 0; nt < 4; nt++)
                    { acc[m][nt][0]=0.f; acc[m][nt][1]=0.f; acc[m][nt][2]=0.f; acc[m][nt][3]=0.f; }
            const uint32_t ab0 = A1u + ((rowoff * STR1 + coloff) << 2);
            const uint32_t ab1 = A1u + (((16 + rowoff) * STR1 + coloff) << 2);
            #pragma unroll
            for (int kp = 0; kp < 8; kp++) {
                uint32_t a0,a1,a2,a3, c0,c1,c2,c3, d0,d1,d2,d3, e0_,e1_,e2_,e3_;
                ldsm4(a0, a1, a2, a3, ab0 + kp * 64);
                ldsm4(c0, c1, c2, c3, ab0 + kp * 64 + 32);
                ldsm4(d0, d1, d2, d3, ab1 + kp * 64);
                ldsm4(e0_, e1_, e2_, e3_, ab1 + kp * 64 + 32);
                #pragma unroll
                for (int nt = 0; nt < 4; nt++) {
                    const uint4 b = __ldg((const uint4*)(Wrcf + (((wl*4+nt)*8+kp)<<7) + lane*4));
                    mma8(acc[0][nt], a0, a1, a2, a3, b.x, b.y);
                    mma8(acc[0][nt], c0, c1, c2, c3, b.z, b.w);
                    mma8(acc[1][nt], d0, d1, d2, d3, b.x, b.y);
                    mma8(acc[1][nt], e0_, e1_, e2_, e3_, b.z, b.w);
                }
            }
            #pragma unroll
            for (int m = 0; m < 2; m++) {
                const int e0 = m * 16 + r, e1 = e0 + 8;
                float* o0 = out + (size_t)(base + e0) * 128;
                float* o1 = out + (size_t)(base + e1) * 128;
                #pragma unroll
                for (int nt = 0; nt < 4; nt++) {
                    const int n0 = (wl * 4 + nt) * 8 + 2 * q;
                    const float2 bb = *(const float2*)(sbrc + n0);
                    if (e0 < n_e) {
                        float2 v;
                        v.x = gelu_f(acc[m][nt][0] + bb.x);
                        v.y = gelu_f(acc[m][nt][1] + bb.y);
                        *(float2*)(o0 + n0) = v;
                    }
                    if (e1 < n_e) {
                        float2 v;
                        v.x = gelu_f(acc[m][nt][2] + bb.x);
                        v.y = gelu_f(acc[m][nt][3] + bb.y);
                        *(float2*)(o1 + n0) = v;
                    }
                }
            }
        }
        GBAR();   // protects A0/sObs/sJ before next tile's stage 0
    }
}

extern "C" void kernel_launch(void* const* d_in, const int* in_sizes, int n_in,
                              void* d_out, int out_size) {
    const float* known_mask   = (const float*)d_in[0];
    const int*   obs_idx      = (const int*)  d_in[1];
    const int*   obs_mask_idx = (const int*)  d_in[2];
    const int*   attr_idx     = (const int*)  d_in[3];
    const float* obs_embs     = (const float*)d_in[4];
    const float* fea_corr     = (const float*)d_in[5];
    const float* W1  = (const float*)d_in[6];
    const float* b1  = (const float*)d_in[7];
    const float* W2  = (const float*)d_in[8];
    const float* b2  = (const float*)d_in[9];
    const float* Wrr = (const float*)d_in[10];
    const float* brr = (const float*)d_in[11];
    const float* Wrc = (const float*)d_in[12];
    const float* brc = (const float*)d_in[13];
    const int E = in_sizes[1];

    int sms = 148;
    cudaDeviceGetAttribute(&sms, cudaDevAttrMultiProcessorCount, 0);
    cudaFuncSetAttribute(attr_rel_mma,
                         cudaFuncAttributeMaxDynamicSharedMemorySize, SMEM_BYTES);

    prep_weights<<<160, 256>>>(W1, W2, Wrr, Wrc);
    attr_rel_mma<<<sms, NTHREADS, SMEM_BYTES>>>(
        known_mask, obs_idx, obs_mask_idx, attr_idx, obs_embs, fea_corr,
        b1, b2, brr, brc,
        (float*)d_out, E);
}

// round 15
// speedup vs baseline: 1.3176x; 1.0657x over previous
#include <cuda_runtime.h>
#include <math.h>
#include <stdint.h>

#define NTHREADS 512
#define NGROUPS  4
#define TILE_E   32          // edges per group-tile

// fragment-ordered tf32 weights in device-global scratch (L1/L2-cached)
// PAIR layout: per (nt, kp) block of 128 words, lane owns words [lane*4..lane*4+3]
#define W1F_OFF   0
#define W2F_OFF   8192
#define WRRF_OFF  16384
#define WRCF_OFF  24576
__device__ __align__(16) uint32_t g_Wf[40960];

// ---------------- smem layout (bytes): activations only ----------------
#define OFF_A0    0                       // 4 x (32 x 68 f)  = 34816
#define OFF_A1    34816                   // 4 x (32 x 132 f) = 67584
#define OFF_B1    102400                  // 128 f
#define OFF_B2    102912                  // 64 f
#define OFF_BRR   103168                  // 128 f
#define OFF_BRC   103680                  // 128 f
#define OFF_OBS   104192                  // 4 x 32 int
#define OFF_J     104704                  // 4 x 32 int
#define SMEM_BYTES 105216

#define STR0 68    // word stride, A0: rows 4 banks apart -> LDSM conflict-free
#define STR1 132   // word stride, A1

// tanh-based GELU via MUFU.TANH
__device__ __forceinline__ float gelu_f(float x) {
    const float k0 = 0.7978845608028654f;
    const float k1 = 0.0356774081f;       // 0.044715 * sqrt(2/pi)
    const float x2 = x * x;
    const float u  = x * fmaf(k1, x2, k0);
    float th;
    asm("tanh.approx.f32 %0, %1;" : "=f"(th) : "f"(u));
    const float hx = 0.5f * x;
    return fmaf(hx, th, hx);
}

__device__ __forceinline__ uint32_t f2tf(float x) {
    uint32_t r;
    asm("cvt.rna.tf32.f32 %0, %1;" : "=r"(r) : "f"(x));
    return r;
}

__device__ __forceinline__ void mma8(float d[4], uint32_t a0, uint32_t a1,
                                     uint32_t a2, uint32_t a3,
                                     uint32_t b0, uint32_t b1) {
    asm volatile(
        "mma.sync.aligned.m16n8k8.row.col.f32.tf32.tf32.f32 "
        "{%0,%1,%2,%3}, {%4,%5,%6,%7}, {%8,%9}, {%0,%1,%2,%3};"
        : "+f"(d[0]), "+f"(d[1]), "+f"(d[2]), "+f"(d[3])
        : "r"(a0), "r"(a1), "r"(a2), "r"(a3), "r"(b0), "r"(b1));
}

__device__ __forceinline__ void ldsm4(uint32_t& a0, uint32_t& a1,
                                      uint32_t& a2, uint32_t& a3, uint32_t addr) {
    asm volatile("ldmatrix.sync.aligned.m8n8.x4.shared.b16 {%0,%1,%2,%3}, [%4];"
                 : "=r"(a0), "=r"(a1), "=r"(a2), "=r"(a3) : "r"(addr));
}

#define GBAR() asm volatile("bar.sync %0, 128;" :: "r"(grp + 1) : "memory")

// one element of W [K,N] row-major -> tf32 B-fragment PAIR order
__device__ __forceinline__ void pf1(const float* __restrict__ W, int K, int N,
                                    uint32_t* __restrict__ dst, int j) {
    const int P    = K >> 4;          // k-step pairs
    const int w    = j & 3;
    const int lane = (j >> 2) & 31;
    const int fp   = j >> 7;
    const int p    = fp % P;
    const int nt   = fp / P;
    const int ks   = 2 * p + (w >> 1);
    const int reg  = w & 1;
    const int k = ks * 8 + (lane & 3) + reg * 4;
    const int n = nt * 8 + (lane >> 2);
    dst[j] = f2tf(W[k * N + n]);
}

__global__ void prep_weights(const float* __restrict__ W1, const float* __restrict__ W2,
                             const float* __restrict__ Wrr, const float* __restrict__ Wrc) {
    int i = blockIdx.x * blockDim.x + threadIdx.x;
    for (; i < 40960; i += gridDim.x * blockDim.x) {
        if (i < 8192)       pf1(W1,   64, 128, g_Wf + W1F_OFF,  i);
        else if (i < 16384) pf1(W2,  128,  64, g_Wf + W2F_OFF,  i - 8192);
        else if (i < 24576) pf1(Wrr,  64, 128, g_Wf + WRRF_OFF, i - 16384);
        else                pf1(Wrc, 128, 128, g_Wf + WRCF_OFF, i - 24576);
    }
}

__global__ void __launch_bounds__(NTHREADS, 1)
attr_rel_mma(const float* __restrict__ km,  const int* __restrict__ obsI,
             const int* __restrict__ omI,   const int* __restrict__ atI,
             const float* __restrict__ obsE, const float* __restrict__ fcorr,
             const float* __restrict__ b1,  const float* __restrict__ b2,
             const float* __restrict__ brr, const float* __restrict__ brc,
             float* __restrict__ out, int E)
{
    extern __shared__ char smem[];
    float* sb1  = (float*)(smem + OFF_B1);
    float* sb2  = (float*)(smem + OFF_B2);
    float* sbrr = (float*)(smem + OFF_BRR);
    float* sbrc = (float*)(smem + OFF_BRC);

    const int tid  = threadIdx.x;
    const int warp = tid >> 5;
    const int lane = tid & 31;
    const int grp  = warp >> 2;          // work-group 0..3
    const int wl   = warp & 3;           // N-group within work-group
    const int tg   = tid & 127;          // thread id within group
    const int r    = lane >> 2;
    const int q    = lane & 3;

    uint32_t* A0 = (uint32_t*)(smem + OFF_A0) + grp * (TILE_E * STR0);
    uint32_t* A1 = (uint32_t*)(smem + OFF_A1) + grp * (TILE_E * STR1);
    int* sObs = (int*)(smem + OFF_OBS) + grp * TILE_E;
    int* sJ   = (int*)(smem + OFF_J)   + grp * TILE_E;

    const uint32_t A0u = (uint32_t)__cvta_generic_to_shared(A0);
    const uint32_t A1u = (uint32_t)__cvta_generic_to_shared(A1);
    const int rowoff = (lane & 7) + ((lane >> 3) & 1) * 8;
    const int coloff = (lane >> 4) << 2;

    const uint32_t* W1f  = g_Wf + W1F_OFF;
    const uint32_t* W2f  = g_Wf + W2F_OFF;
    const uint32_t* Wrrf = g_Wf + WRRF_OFF;
    const uint32_t* Wrcf = g_Wf + WRCF_OFF;

    for (int i = tid; i < 128; i += NTHREADS) sb1[i]  = b1[i];
    for (int i = tid; i < 64;  i += NTHREADS) sb2[i]  = b2[i];
    for (int i = tid; i < 128; i += NTHREADS) sbrr[i] = brr[i];
    for (int i = tid; i < 128; i += NTHREADS) sbrc[i] = brc[i];
    __syncthreads();

    const int ntiles = (E + TILE_E - 1) / TILE_E;

    for (int tile = blockIdx.x * NGROUPS + grp; tile < ntiles; tile += gridDim.x * NGROUPS) {
        const int base = tile * TILE_E;
        const int n_e  = min(TILE_E, E - base);

        // ---- stage 0: X = softmax(m_i*m_j) closed form -> A0 ----
        {
            const int e  = tg >> 2;
            const int qq = tg & 3;
            const int eg = base + (e < n_e ? e : n_e - 1);
            const int mrowi = omI[eg];
            const int jj    = atI[eg];
            if (qq == 0) { sObs[e] = obsI[eg]; sJ[e] = jj; }
            const float* mrow = km + (size_t)mrowi * 64;
            float mv[16];
            float s = 0.f;
            #pragma unroll
            for (int t = 0; t < 4; t++) {
                float4 v = *(const float4*)(mrow + qq * 16 + t * 4);
                mv[t*4+0]=v.x; mv[t*4+1]=v.y; mv[t*4+2]=v.z; mv[t*4+3]=v.w;
                s += v.x + v.y + v.z + v.w;
            }
            s += __shfl_xor_sync(0xffffffffu, s, 1);
            s += __shfl_xor_sync(0xffffffffu, s, 2);
            const float kn = s - mrow[jj];
            const float EU = 2.71828182845904523536f;
            const float alpha = 1.f / (kn * EU + (64.f - kn));
            const uint32_t ua = f2tf(alpha);
            const uint32_t ub = f2tf(EU * alpha);
            uint32_t w[16];
            #pragma unroll
            for (int t = 0; t < 16; t++) {
                const int f = qq * 16 + t;
                w[t] = (mv[t] != 0.f && f != jj) ? ub : ua;
            }
            uint4* dst = (uint4*)(A0 + e * STR0 + qq * 16);
            dst[0] = make_uint4(w[0],  w[1],  w[2],  w[3]);
            dst[1] = make_uint4(w[4],  w[5],  w[6],  w[7]);
            dst[2] = make_uint4(w[8],  w[9],  w[10], w[11]);
            dst[3] = make_uint4(w[12], w[13], w[14], w[15]);
        }
        GBAR();

        // ---- stage 1: H = gelu(X @ W1 + b1) -> A1   (K=64, N=128) ----
        {
            float acc[2][4][4];
            #pragma unroll
            for (int m = 0; m < 2; m++)
                #pragma unroll
                for (int nt = 0; nt < 4; nt++)
                    { acc[m][nt][0]=0.f; acc[m][nt][1]=0.f; acc[m][nt][2]=0.f; acc[m][nt][3]=0.f; }
            #pragma unroll
            for (int m = 0; m < 2; m++) {
                const uint32_t ab = A0u + (((m * 16 + rowoff) * STR0 + coloff) << 2);
                #pragma unroll
                for (int kp = 0; kp < 4; kp++) {
                    uint32_t a0, a1, a2, a3, c0, c1, c2, c3;
                    ldsm4(a0, a1, a2, a3, ab + kp * 64);
                    ldsm4(c0, c1, c2, c3, ab + kp * 64 + 32);
                    #pragma unroll
                    for (int nt = 0; nt < 4; nt++) {
                        const uint4 b = __ldg((const uint4*)(W1f + (((wl*4+nt)*4+kp)<<7) + lane*4));
                        mma8(acc[m][nt], a0, a1, a2, a3, b.x, b.y);
                        mma8(acc[m][nt], c0, c1, c2, c3, b.z, b.w);
                    }
                }
            }
            #pragma unroll
            for (int m = 0; m < 2; m++) {
                const int e0 = m * 16 + r;
                #pragma unroll
                for (int nt = 0; nt < 4; nt++) {
                    const int n0 = (wl * 4 + nt) * 8 + 2 * q;
                    const float2 bb = *(const float2*)(sb1 + n0);
                    uint2 lo, hi;
                    lo.x = __float_as_uint(gelu_f(acc[m][nt][0] + bb.x));
                    lo.y = __float_as_uint(gelu_f(acc[m][nt][1] + bb.y));
                    hi.x = __float_as_uint(gelu_f(acc[m][nt][2] + bb.x));
                    hi.y = __float_as_uint(gelu_f(acc[m][nt][3] + bb.y));
                    *(uint2*)(A1 + e0 * STR1 + n0)       = lo;
                    *(uint2*)(A1 + (e0 + 8) * STR1 + n0) = hi;
                }
            }
        }
        GBAR();

        // ---- stage 2: T = fea_corr[j] * gelu(H @ W2 + b2) -> A0   (K=128, N=64) ----
        {
            float acc[2][2][4];
            #pragma unroll
            for (int m = 0; m < 2; m++)
                #pragma unroll
                for (int nt = 0; nt < 2; nt++)
                    { acc[m][nt][0]=0.f; acc[m][nt][1]=0.f; acc[m][nt][2]=0.f; acc[m][nt][3]=0.f; }
            #pragma unroll
            for (int m = 0; m < 2; m++) {
                const uint32_t ab = A1u + (((m * 16 + rowoff) * STR1 + coloff) << 2);
                #pragma unroll
                for (int kp = 0; kp < 8; kp++) {
                    uint32_t a0, a1, a2, a3, c0, c1, c2, c3;
                    ldsm4(a0, a1, a2, a3, ab + kp * 64);
                    ldsm4(c0, c1, c2, c3, ab + kp * 64 + 32);
                    #pragma unroll
                    for (int nt = 0; nt < 2; nt++) {
                        const uint4 b = __ldg((const uint4*)(W2f + (((wl*2+nt)*8+kp)<<7) + lane*4));
                        mma8(acc[m][nt], a0, a1, a2, a3, b.x, b.y);
                        mma8(acc[m][nt], c0, c1, c2, c3, b.z, b.w);
                    }
                }
            }
            #pragma unroll
            for (int m = 0; m < 2; m++) {
                const int e0 = m * 16 + r, e1 = e0 + 8;
                const int j0 = sJ[e0], j1 = sJ[e1];
                #pragma unroll
                for (int nt = 0; nt < 2; nt++) {
                    const int n0 = (wl * 2 + nt) * 8 + 2 * q;
                    const float2 bb = *(const float2*)(sb2 + n0);
                    const float2 f0 = __ldg((const float2*)(fcorr + (size_t)j0 * 64 + n0));
                    const float2 f1 = __ldg((const float2*)(fcorr + (size_t)j1 * 64 + n0));
                    uint2 lo, hi;
                    lo.x = __float_as_uint(f0.x * gelu_f(acc[m][nt][0] + bb.x));
                    lo.y = __float_as_uint(f0.y * gelu_f(acc[m][nt][1] + bb.y));
                    hi.x = __float_as_uint(f1.x * gelu_f(acc[m][nt][2] + bb.x));
                    hi.y = __float_as_uint(f1.y * gelu_f(acc[m][nt][3] + bb.y));
                    *(uint2*)(A0 + e0 * STR0 + n0) = lo;
                    *(uint2*)(A0 + e1 * STR0 + n0) = hi;
                }
            }
        }
        GBAR();

        // ---- stage 3: U = obs_h * gelu(T @ Wrr + brr) -> A1   (K=64, N=128) ----
        {
            float acc[2][4][4];
            #pragma unroll
            for (int m = 0; m < 2; m++)
                #pragma unroll
                for (int nt = 0; nt < 4; nt++)
                    { acc[m][nt][0]=0.f; acc[m][nt][1]=0.f; acc[m][nt][2]=0.f; acc[m][nt][3]=0.f; }
            #pragma unroll
            for (int m = 0; m < 2; m++) {
                const uint32_t ab = A0u + (((m * 16 + rowoff) * STR0 + coloff) << 2);
                #pragma unroll
                for (int kp = 0; kp < 4; kp++) {
                    uint32_t a0, a1, a2, a3, c0, c1, c2, c3;
                    ldsm4(a0, a1, a2, a3, ab + kp * 64);
                    ldsm4(c0, c1, c2, c3, ab + kp * 64 + 32);
                    #pragma unroll
                    for (int nt = 0; nt < 4; nt++) {
                        const uint4 b = __ldg((const uint4*)(Wrrf + (((wl*4+nt)*4+kp)<<7) + lane*4));
                        mma8(acc[m][nt], a0, a1, a2, a3, b.x, b.y);
                        mma8(acc[m][nt], c0, c1, c2, c3, b.z, b.w);
                    }
                }
            }
            #pragma unroll
            for (int m = 0; m < 2; m++) {
                const int e0 = m * 16 + r, e1 = e0 + 8;
                const size_t o0 = (size_t)sObs[e0] * 128;
                const size_t o1 = (size_t)sObs[e1] * 128;
                #pragma unroll
                for (int nt = 0; nt < 4; nt++) {
                    const int n0 = (wl * 4 + nt) * 8 + 2 * q;
                    const float2 bb = *(const float2*)(sbrr + n0);
                    const float2 v0 = __ldg((const float2*)(obsE + o0 + n0));
                    const float2 v1 = __ldg((const float2*)(obsE + o1 + n0));
                    uint2 lo, hi;
                    lo.x = __float_as_uint(v0.x * gelu_f(acc[m][nt][0] + bb.x));
                    lo.y = __float_as_uint(v0.y * gelu_f(acc[m][nt][1] + bb.y));
                    hi.x = __float_as_uint(v1.x * gelu_f(acc[m][nt][2] + bb.x));
                    hi.y = __float_as_uint(v1.y * gelu_f(acc[m][nt][3] + bb.y));
                    *(uint2*)(A1 + e0 * STR1 + n0) = lo;
                    *(uint2*)(A1 + e1 * STR1 + n0) = hi;
                }
            }
        }
        GBAR();

        // ---- stage 4: out = gelu(U @ Wrc + brc) -> global   (K=128, N=128) ----
        {
            float acc[2][4][4];
            #pragma unroll
            for (int m = 0; m < 2; m++)
                #pragma unroll
                for (int nt = 0; nt < 4; nt++)
                    { acc[m][nt][0]=0.f; acc[m][nt][1]=0.f; acc[m][nt][2]=0.f; acc[m][nt][3]=0.f; }
            #pragma unroll
            for (int m = 0; m < 2; m++) {
                const uint32_t ab = A1u + (((m * 16 + rowoff) * STR1 + coloff) << 2);
                #pragma unroll
                for (int kp = 0; kp < 8; kp++) {
                    uint32_t a0, a1, a2, a3, c0, c1, c2, c3;
                    ldsm4(a0, a1, a2, a3, ab + kp * 64);
                    ldsm4(c0, c1, c2, c3, ab + kp * 64 + 32);
                    #pragma unroll
                    for (int nt = 0; nt < 4; nt++) {
                        const uint4 b = __ldg((const uint4*)(Wrcf + (((wl*4+nt)*8+kp)<<7) + lane*4));
                        mma8(acc[m][nt], a0, a1, a2, a3, b.x, b.y);
                        mma8(acc[m][nt], c0, c1, c2, c3, b.z, b.w);
                    }
                }
            }
            #pragma unroll
            for (int m = 0; m < 2; m++) {
                const int e0 = m * 16 + r, e1 = e0 + 8;
                float* o0 = out + (size_t)(base + e0) * 128;
                float* o1 = out + (size_t)(base + e1) * 128;
                #pragma unroll
                for (int nt = 0; nt < 4; nt++) {
                    const int n0 = (wl * 4 + nt) * 8 + 2 * q;
                    const float2 bb = *(const float2*)(sbrc + n0);
                    if (e0 < n_e) {
                        float2 v;
                        v.x = gelu_f(acc[m][nt][0] + bb.x);
                        v.y = gelu_f(acc[m][nt][1] + bb.y);
                        *(float2*)(o0 + n0) = v;
                    }
                    if (e1 < n_e) {
                        float2 v;
                        v.x = gelu_f(acc[m][nt][2] + bb.x);
                        v.y = gelu_f(acc[m][nt][3] + bb.y);
                        *(float2*)(o1 + n0) = v;
                    }
                }
            }
        }
        GBAR();   // protects A0/sObs/sJ before next tile's stage 0
    }
}

extern "C" void kernel_launch(void* const* d_in, const int* in_sizes, int n_in,
                              void* d_out, int out_size) {
    const float* known_mask   = (const float*)d_in[0];
    const int*   obs_idx      = (const int*)  d_in[1];
    const int*   obs_mask_idx = (const int*)  d_in[2];
    const int*   attr_idx     = (const int*)  d_in[3];
    const float* obs_embs     = (const float*)d_in[4];
    const float* fea_corr     = (const float*)d_in[5];
    const float* W1  = (const float*)d_in[6];
    const float* b1  = (const float*)d_in[7];
    const float* W2  = (const float*)d_in[8];
    const float* b2  = (const float*)d_in[9];
    const float* Wrr = (const float*)d_in[10];
    const float* brr = (const float*)d_in[11];
    const float* Wrc = (const float*)d_in[12];
    const float* brc = (const float*)d_in[13];
    const int E = in_sizes[1];

    int sms = 148;
    cudaDeviceGetAttribute(&sms, cudaDevAttrMultiProcessorCount, 0);
    cudaFuncSetAttribute(attr_rel_mma,
                         cudaFuncAttributeMaxDynamicSharedMemorySize, SMEM_BYTES);

    prep_weights<<<160, 256>>>(W1, W2, Wrr, Wrc);
    attr_rel_mma<<<sms, NTHREADS, SMEM_BYTES>>>(
        known_mask, obs_idx, obs_mask_idx, attr_idx, obs_embs, fea_corr,
        b1, b2, brr, brc,
        (float*)d_out, E);
}

// round 16
// speedup vs baseline: 2.0028x; 1.5200x over previous
#include <cuda_runtime.h>
#include <cuda_fp16.h>
#include <math.h>
#include <stdint.h>

#define NTHREADS 512
#define NGROUPS  4
#define TILE_E   32          // edges per group-tile

// fp16 fragment-ordered weights in device-global scratch (L1-resident, 80 KB)
// per (nt,kp) block of 128 words; lane owns words [lane*4..lane*4+3] =
//   { ks=2kp:   b0=(W[k0][n],W[k0+1][n]), b1=(W[k0+8][n],W[k0+9][n]),
//     ks=2kp+1: b0, b1 }   with k0 = 16*ks + 2*(lane&3), n = nt*8 + (lane>>2)
#define W1H_OFF   0
#define W2H_OFF   4096
#define WRRH_OFF  8192
#define WRCH_OFF  12288
__device__ __align__(16) uint32_t g_Wf[20480];

// ---------------- smem layout (bytes) ----------------
// A0: 32 rows x 144 B (64 fp16 + 16B pad)  A1: 32 rows x 272 B (128 fp16 + 16B pad)
#define STRB0 144
#define STRB1 272
#define OFF_A0    0                       // 4 x 4608  = 18432
#define OFF_A1    18432                   // 4 x 8704  = 34816
#define OFF_B1    53248                   // 128 f
#define OFF_B2    53760                   // 64 f
#define OFF_BRR   54016                   // 128 f
#define OFF_BRC   54528                   // 128 f
#define OFF_OBS   55040                   // 4 x 32 int
#define OFF_J     55552                   // 4 x 32 int
#define SMEM_BYTES 56064

// tanh-based GELU via MUFU.TANH
__device__ __forceinline__ float gelu_f(float x) {
    const float k0 = 0.7978845608028654f;
    const float k1 = 0.0356774081f;
    const float x2 = x * x;
    const float u  = x * fmaf(k1, x2, k0);
    float th;
    asm("tanh.approx.f32 %0, %1;" : "=f"(th) : "f"(u));
    const float hx = 0.5f * x;
    return fmaf(hx, th, hx);
}

__device__ __forceinline__ void mma16(float d[4], uint32_t a0, uint32_t a1,
                                      uint32_t a2, uint32_t a3,
                                      uint32_t b0, uint32_t b1) {
    asm volatile(
        "mma.sync.aligned.m16n8k16.row.col.f32.f16.f16.f32 "
        "{%0,%1,%2,%3}, {%4,%5,%6,%7}, {%8,%9}, {%0,%1,%2,%3};"
        : "+f"(d[0]), "+f"(d[1]), "+f"(d[2]), "+f"(d[3])
        : "r"(a0), "r"(a1), "r"(a2), "r"(a3), "r"(b0), "r"(b1));
}

__device__ __forceinline__ void ldsm4(uint32_t& a0, uint32_t& a1,
                                      uint32_t& a2, uint32_t& a3, uint32_t addr) {
    asm volatile("ldmatrix.sync.aligned.m8n8.x4.shared.b16 {%0,%1,%2,%3}, [%4];"
                 : "=r"(a0), "=r"(a1), "=r"(a2), "=r"(a3) : "r"(addr));
}

__device__ __forceinline__ uint32_t pack2(float x, float y) {
    __half2 h = __floats2half2_rn(x, y);
    return *(uint32_t*)&h;
}

#define GBAR() asm volatile("bar.sync %0, 128;" :: "r"(grp + 1) : "memory")

// one u32 word of W [K,N] row-major -> fp16 B-fragment PAIR order
__device__ __forceinline__ void pf1h(const float* __restrict__ W, int K, int N,
                                     uint32_t* __restrict__ dst, int j) {
    const int KP   = K >> 5;          // k16-step pairs
    const int w    = j & 3;
    const int lane = (j >> 2) & 31;
    const int fp   = j >> 7;
    const int kp   = fp % KP;
    const int nt   = fp / KP;
    const int ks   = 2 * kp + (w >> 1);
    const int reg  = w & 1;
    const int q    = lane & 3;
    const int n    = nt * 8 + (lane >> 2);
    const int k0   = ks * 16 + 2 * q + reg * 8;
    dst[j] = pack2(W[k0 * N + n], W[(k0 + 1) * N + n]);
}

__global__ void prep_weights(const float* __restrict__ W1, const float* __restrict__ W2,
                             const float* __restrict__ Wrr, const float* __restrict__ Wrc) {
    int i = blockIdx.x * blockDim.x + threadIdx.x;
    for (; i < 20480; i += gridDim.x * blockDim.x) {
        if (i < 4096)       pf1h(W1,   64, 128, g_Wf + W1H_OFF,  i);
        else if (i < 8192)  pf1h(W2,  128,  64, g_Wf + W2H_OFF,  i - 4096);
        else if (i < 12288) pf1h(Wrr,  64, 128, g_Wf + WRRH_OFF, i - 8192);
        else                pf1h(Wrc, 128, 128, g_Wf + WRCH_OFF, i - 12288);
    }
}

__global__ void __launch_bounds__(NTHREADS, 1)
attr_rel_mma(const float* __restrict__ km,  const int* __restrict__ obsI,
             const int* __restrict__ omI,   const int* __restrict__ atI,
             const float* __restrict__ obsE, const float* __restrict__ fcorr,
             const float* __restrict__ b1,  const float* __restrict__ b2,
             const float* __restrict__ brr, const float* __restrict__ brc,
             float* __restrict__ out, int E)
{
    extern __shared__ char smem[];
    float* sb1  = (float*)(smem + OFF_B1);
    float* sb2  = (float*)(smem + OFF_B2);
    float* sbrr = (float*)(smem + OFF_BRR);
    float* sbrc = (float*)(smem + OFF_BRC);

    const int tid  = threadIdx.x;
    const int warp = tid >> 5;
    const int lane = tid & 31;
    const int grp  = warp >> 2;          // work-group 0..3
    const int wl   = warp & 3;           // N-group within work-group
    const int tg   = tid & 127;          // thread id within group
    const int r    = lane >> 2;
    const int q    = lane & 3;

    char* A0c = smem + OFF_A0 + grp * (TILE_E * STRB0);
    char* A1c = smem + OFF_A1 + grp * (TILE_E * STRB1);
    int* sObs = (int*)(smem + OFF_OBS) + grp * TILE_E;
    int* sJ   = (int*)(smem + OFF_J)   + grp * TILE_E;

    const uint32_t A0u = (uint32_t)__cvta_generic_to_shared(A0c);
    const uint32_t A1u = (uint32_t)__cvta_generic_to_shared(A1c);
    const int rowoff  = (lane & 7) + ((lane >> 3) & 1) * 8;
    const int coloffB = (lane >> 4) * 16;     // byte offset into the k16 row chunk

    const uint32_t* W1h  = g_Wf + W1H_OFF;
    const uint32_t* W2h  = g_Wf + W2H_OFF;
    const uint32_t* Wrrh = g_Wf + WRRH_OFF;
    const uint32_t* Wrch = g_Wf + WRCH_OFF;

    for (int i = tid; i < 128; i += NTHREADS) sb1[i]  = b1[i];
    for (int i = tid; i < 64;  i += NTHREADS) sb2[i]  = b2[i];
    for (int i = tid; i < 128; i += NTHREADS) sbrr[i] = brr[i];
    for (int i = tid; i < 128; i += NTHREADS) sbrc[i] = brc[i];
    __syncthreads();

    const int ntiles = (E + TILE_E - 1) / TILE_E;

    for (int tile = blockIdx.x * NGROUPS + grp; tile < ntiles; tile += gridDim.x * NGROUPS) {
        const int base = tile * TILE_E;
        const int n_e  = min(TILE_E, E - base);

        // ---- stage 0: X = softmax(m_i*m_j) closed form -> A0 (fp16) ----
        {
            const int e  = tg >> 2;
            const int qq = tg & 3;
            const int eg = base + (e < n_e ? e : n_e - 1);
            const int mrowi = omI[eg];
            const int jj    = atI[eg];
            if (qq == 0) { sObs[e] = obsI[eg]; sJ[e] = jj; }
            const float* mrow = km + (size_t)mrowi * 64;
            float mv[16];
            float s = 0.f;
            #pragma unroll
            for (int t = 0; t < 4; t++) {
                float4 v = *(const float4*)(mrow + qq * 16 + t * 4);
                mv[t*4+0]=v.x; mv[t*4+1]=v.y; mv[t*4+2]=v.z; mv[t*4+3]=v.w;
                s += v.x + v.y + v.z + v.w;
            }
            s += __shfl_xor_sync(0xffffffffu, s, 1);
            s += __shfl_xor_sync(0xffffffffu, s, 2);
            const float kn = s - mrow[jj];
            const float EU = 2.71828182845904523536f;
            const float alpha = 1.f / (kn * EU + (64.f - kn));
            const float beta  = EU * alpha;
            uint32_t w[8];
            #pragma unroll
            for (int t = 0; t < 8; t++) {
                const int f0 = qq * 16 + 2 * t;
                const float v0 = (mv[2*t]   != 0.f && (f0)   != jj) ? beta : alpha;
                const float v1 = (mv[2*t+1] != 0.f && (f0+1) != jj) ? beta : alpha;
                w[t] = pack2(v0, v1);
            }
            uint4* dst = (uint4*)(A0c + e * STRB0 + qq * 32);
            dst[0] = make_uint4(w[0], w[1], w[2], w[3]);
            dst[1] = make_uint4(w[4], w[5], w[6], w[7]);
        }
        GBAR();

        // ---- stage 1: H = gelu(X @ W1 + b1) -> A1   (K=64, N=128) ----
        {
            float acc[2][4][4];
            #pragma unroll
            for (int m = 0; m < 2; m++)
                #pragma unroll
                for (int nt = 0; nt < 4; nt++)
                    { acc[m][nt][0]=0.f; acc[m][nt][1]=0.f; acc[m][nt][2]=0.f; acc[m][nt][3]=0.f; }
            #pragma unroll
            for (int m = 0; m < 2; m++) {
                const uint32_t ab = A0u + (m * 16 + rowoff) * STRB0 + coloffB;
                #pragma unroll
                for (int kp = 0; kp < 2; kp++) {
                    uint32_t a0, a1, a2, a3, c0, c1, c2, c3;
                    ldsm4(a0, a1, a2, a3, ab + (2 * kp) * 32);
                    ldsm4(c0, c1, c2, c3, ab + (2 * kp + 1) * 32);
                    #pragma unroll
                    for (int nt = 0; nt < 4; nt++) {
                        const uint4 b = __ldg((const uint4*)(W1h + (((wl*4+nt)*2+kp)<<7) + lane*4));
                        mma16(acc[m][nt], a0, a1, a2, a3, b.x, b.y);
                        mma16(acc[m][nt], c0, c1, c2, c3, b.z, b.w);
                    }
                }
            }
            #pragma unroll
            for (int m = 0; m < 2; m++) {
                const int e0 = m * 16 + r;
                #pragma unroll
                for (int nt = 0; nt < 4; nt++) {
                    const int n0 = (wl * 4 + nt) * 8 + 2 * q;
                    const float2 bb = *(const float2*)(sb1 + n0);
                    *(uint32_t*)(A1c + e0 * STRB1 + n0 * 2) =
                        pack2(gelu_f(acc[m][nt][0] + bb.x), gelu_f(acc[m][nt][1] + bb.y));
                    *(uint32_t*)(A1c + (e0 + 8) * STRB1 + n0 * 2) =
                        pack2(gelu_f(acc[m][nt][2] + bb.x), gelu_f(acc[m][nt][3] + bb.y));
                }
            }
        }
        GBAR();

        // ---- stage 2: T = fea_corr[j] * gelu(H @ W2 + b2) -> A0   (K=128, N=64) ----
        {
            float acc[2][2][4];
            #pragma unroll
            for (int m = 0; m < 2; m++)
                #pragma unroll
                for (int nt = 0; nt < 2; nt++)
                    { acc[m][nt][0]=0.f; acc[m][nt][1]=0.f; acc[m][nt][2]=0.f; acc[m][nt][3]=0.f; }
            #pragma unroll
            for (int m = 0; m < 2; m++) {
                const uint32_t ab = A1u + (m * 16 + rowoff) * STRB1 + coloffB;
                #pragma unroll
                for (int kp = 0; kp < 4; kp++) {
                    uint32_t a0, a1, a2, a3, c0, c1, c2, c3;
                    ldsm4(a0, a1, a2, a3, ab + (2 * kp) * 32);
                    ldsm4(c0, c1, c2, c3, ab + (2 * kp + 1) * 32);
                    #pragma unroll
                    for (int nt = 0; nt < 2; nt++) {
                        const uint4 b = __ldg((const uint4*)(W2h + (((wl*2+nt)*4+kp)<<7) + lane*4));
                        mma16(acc[m][nt], a0, a1, a2, a3, b.x, b.y);
                        mma16(acc[m][nt], c0, c1, c2, c3, b.z, b.w);
                    }
                }
            }
            #pragma unroll
            for (int m = 0; m < 2; m++) {
                const int e0 = m * 16 + r, e1 = e0 + 8;
                const int j0 = sJ[e0], j1 = sJ[e1];
                #pragma unroll
                for (int nt = 0; nt < 2; nt++) {
                    const int n0 = (wl * 2 + nt) * 8 + 2 * q;
                    const float2 bb = *(const float2*)(sb2 + n0);
                    const float2 f0 = __ldg((const float2*)(fcorr + (size_t)j0 * 64 + n0));
                    const float2 f1 = __ldg((const float2*)(fcorr + (size_t)j1 * 64 + n0));
                    *(uint32_t*)(A0c + e0 * STRB0 + n0 * 2) =
                        pack2(f0.x * gelu_f(acc[m][nt][0] + bb.x),
                              f0.y * gelu_f(acc[m][nt][1] + bb.y));
                    *(uint32_t*)(A0c + e1 * STRB0 + n0 * 2) =
                        pack2(f1.x * gelu_f(acc[m][nt][2] + bb.x),
                              f1.y * gelu_f(acc[m][nt][3] + bb.y));
                }
            }
        }
        GBAR();

        // ---- stage 3: U = obs_h * gelu(T @ Wrr + brr) -> A1   (K=64, N=128) ----
        {
            float acc[2][4][4];
            #pragma unroll
            for (int m = 0; m < 2; m++)
                #pragma unroll
                for (int nt = 0; nt < 4; nt++)
                    { acc[m][nt][0]=0.f; acc[m][nt][1]=0.f; acc[m][nt][2]=0.f; acc[m][nt][3]=0.f; }
            #pragma unroll
            for (int m = 0; m < 2; m++) {
                const uint32_t ab = A0u + (m * 16 + rowoff) * STRB0 + coloffB;
                #pragma unroll
                for (int kp = 0; kp < 2; kp++) {
                    uint32_t a0, a1, a2, a3, c0, c1, c2, c3;
                    ldsm4(a0, a1, a2, a3, ab + (2 * kp) * 32);
                    ldsm4(c0, c1, c2, c3, ab + (2 * kp + 1) * 32);
                    #pragma unroll
                    for (int nt = 0; nt < 4; nt++) {
                        const uint4 b = __ldg((const uint4*)(Wrrh + (((wl*4+nt)*2+kp)<<7) + lane*4));
                        mma16(acc[m][nt], a0, a1, a2, a3, b.x, b.y);
                        mma16(acc[m][nt], c0, c1, c2, c3, b.z, b.w);
                    }
                }
            }
            #pragma unroll
            for (int m = 0; m < 2; m++) {
                const int e0 = m * 16 + r, e1 = e0 + 8;
                const size_t o0 = (size_t)sObs[e0] * 128;
                const size_t o1 = (size_t)sObs[e1] * 128;
                #pragma unroll
                for (int nt = 0; nt < 4; nt++) {
                    const int n0 = (wl * 4 + nt) * 8 + 2 * q;
                    const float2 bb = *(const float2*)(sbrr + n0);
                    const float2 v0 = __ldg((const float2*)(obsE + o0 + n0));
                    const float2 v1 = __ldg((const float2*)(obsE + o1 + n0));
                    *(uint32_t*)(A1c + e0 * STRB1 + n0 * 2) =
                        pack2(v0.x * gelu_f(acc[m][nt][0] + bb.x),
                              v0.y * gelu_f(acc[m][nt][1] + bb.y));
                    *(uint32_t*)(A1c + e1 * STRB1 + n0 * 2) =
                        pack2(v1.x * gelu_f(acc[m][nt][2] + bb.x),
                              v1.y * gelu_f(acc[m][nt][3] + bb.y));
                }
            }
        }
        GBAR();

        // ---- stage 4: out = gelu(U @ Wrc + brc) -> global   (K=128, N=128) ----
        {
            float acc[2][4][4];
            #pragma unroll
            for (int m = 0; m < 2; m++)
                #pragma unroll
                for (int nt = 0; nt < 4; nt++)
                    { acc[m][nt][0]=0.f; acc[m][nt][1]=0.f; acc[m][nt][2]=0.f; acc[m][nt][3]=0.f; }
            #pragma unroll
            for (int m = 0; m < 2; m++) {
                const uint32_t ab = A1u + (m * 16 + rowoff) * STRB1 + coloffB;
                #pragma unroll
                for (int kp = 0; kp < 4; kp++) {
                    uint32_t a0, a1, a2, a3, c0, c1, c2, c3;
                    ldsm4(a0, a1, a2, a3, ab + (2 * kp) * 32);
                    ldsm4(c0, c1, c2, c3, ab + (2 * kp + 1) * 32);
                    #pragma unroll
                    for (int nt = 0; nt < 4; nt++) {
                        const uint4 b = __ldg((const uint4*)(Wrch + (((wl*4+nt)*4+kp)<<7) + lane*4));
                        mma16(acc[m][nt], a0, a1, a2, a3, b.x, b.y);
                        mma16(acc[m][nt], c0, c1, c2, c3, b.z, b.w);
                    }
                }
            }
            #pragma unroll
            for (int m = 0; m < 2; m++) {
                const int e0 = m * 16 + r, e1 = e0 + 8;
                float* o0 = out + (size_t)(base + e0) * 128;
                float* o1 = out + (size_t)(base + e1) * 128;
                #pragma unroll
                for (int nt = 0; nt < 4; nt++) {
                    const int n0 = (wl * 4 + nt) * 8 + 2 * q;
                    const float2 bb = *(const float2*)(sbrc + n0);
                    if (e0 < n_e) {
                        float2 v;
                        v.x = gelu_f(acc[m][nt][0] + bb.x);
                        v.y = gelu_f(acc[m][nt][1] + bb.y);
                        *(float2*)(o0 + n0) = v;
                    }
                    if (e1 < n_e) {
                        float2 v;
                        v.x = gelu_f(acc[m][nt][2] + bb.x);
                        v.y = gelu_f(acc[m][nt][3] + bb.y);
                        *(float2*)(o1 + n0) = v;
                    }
                }
            }
        }
        GBAR();   // protects A0/sObs/sJ before next tile's stage 0
    }
}

extern "C" void kernel_launch(void* const* d_in, const int* in_sizes, int n_in,
                              void* d_out, int out_size) {
    const float* known_mask   = (const float*)d_in[0];
    const int*   obs_idx      = (const int*)  d_in[1];
    const int*   obs_mask_idx = (const int*)  d_in[2];
    const int*   attr_idx     = (const int*)  d_in[3];
    const float* obs_embs     = (const float*)d_in[4];
    const float* fea_corr     = (const float*)d_in[5];
    const float* W1  = (const float*)d_in[6];
    const float* b1  = (const float*)d_in[7];
    const float* W2  = (const float*)d_in[8];
    const float* b2  = (const float*)d_in[9];
    const float* Wrr = (const float*)d_in[10];
    const float* brr = (const float*)d_in[11];
    const float* Wrc = (const float*)d_in[12];
    const float* brc = (const float*)d_in[13];
    const int E = in_sizes[1];

    int sms = 148;
    cudaDeviceGetAttribute(&sms, cudaDevAttrMultiProcessorCount, 0);
    cudaFuncSetAttribute(attr_rel_mma,
                         cudaFuncAttributeMaxDynamicSharedMemorySize, SMEM_BYTES);

    prep_weights<<<160, 256>>>(W1, W2, Wrr, Wrc);
    attr_rel_mma<<<sms, NTHREADS, SMEM_BYTES>>>(
        known_mask, obs_idx, obs_mask_idx, attr_idx, obs_embs, fea_corr,
        b1, b2, brr, brc,
        (float*)d_out, E);
}